// round 14
// baseline (speedup 1.0000x reference)
#include <cuda_runtime.h>

// PinnWithGRU: B=2048 seqs, T=2048 steps, D=3, H=32.
// One warp per sequence, one hidden unit per lane.
// KEY CHANGE (R14): 128-thread CTAs (4 warps). B300 assigns warp->SMSP by
// (warp-id-in-block % 4); the previous 2-warp CTAs put every warp on SMSP 0/1
// and left SMSP 2/3 idle -- both prior rounds were FMA-pipe-saturated on half
// the SM. 4-warp CTAs halve the per-SMSP pipe load.
// Hidden GEMV via packed f32x2 FFMA2 (even/odd k-split), weights pre-scaled
// by -log2e / -2log2e so activations are rcp(1+ex2(acc)).
#define BB 2048
#define TT 2048
#define DD 3
#define HH 32

using ull = unsigned long long;

__device__ __forceinline__ ull ffma2(ull a, ull b, ull c) {
    ull d;
    asm("fma.rn.f32x2 %0, %1, %2, %3;" : "=l"(d) : "l"(a), "l"(b), "l"(c));
    return d;
}
__device__ __forceinline__ ull pack2(float lo, float hi) {
    ull r;
    asm("mov.b64 %0, {%1, %2};" : "=l"(r) : "f"(lo), "f"(hi));
    return r;
}
__device__ __forceinline__ void unpack2(ull v, float& lo, float& hi) {
    asm("mov.b64 {%0, %1}, %2;" : "=f"(lo), "=f"(hi) : "l"(v));
}
__device__ __forceinline__ float ex2f(float x) {
    float y; asm("ex2.approx.f32 %0, %1;" : "=f"(y) : "f"(x)); return y;
}
__device__ __forceinline__ float rcpf(float x) {
    float y; asm("rcp.approx.f32 %0, %1;" : "=f"(y) : "f"(x)); return y;
}

__global__ __launch_bounds__(128)
void gru_scan_kernel(const float* __restrict__ inp,     // [B, T, 3]
                     const float* __restrict__ Wih,     // [96, 3]
                     const float* __restrict__ Whh,     // [96, 32]
                     const float* __restrict__ bias,    // [96]
                     const float* __restrict__ bias_n,  // [32]
                     float* __restrict__ out)           // [B, T]
{
    const int lane = threadIdx.x & 31;
    const int wid  = threadIdx.x >> 5;            // warp in CTA (0..3) -> SMSP 0..3
    const int b    = blockIdx.x * 4 + wid;
    if (b >= BB) return;

    __shared__ __align__(16) float hsh[4][2][HH];  // [warp][buffer][unit]

    const float L2E = 1.4426950408889634f;
    const float cRZ = -L2E;          // sigmoid gates: acc = -log2e * pre-act
    const float cA  = -2.0f * L2E;   // tanh gate:     acc = -2log2e * pre-act

    // --- W_hh rows for this lane, pre-scaled, packed (even k, odd k) ---
    ull wr2[16], wz2[16], wa2[16];
    const float4* whh4 = reinterpret_cast<const float4*>(Whh);
    #pragma unroll
    for (int k4 = 0; k4 < 8; k4++) {
        float4 v;
        v = whh4[(0 * HH + lane) * 8 + k4];
        wr2[2*k4]   = pack2(cRZ * v.x, cRZ * v.y);
        wr2[2*k4+1] = pack2(cRZ * v.z, cRZ * v.w);
        v = whh4[(1 * HH + lane) * 8 + k4];
        wz2[2*k4]   = pack2(cRZ * v.x, cRZ * v.y);
        wz2[2*k4+1] = pack2(cRZ * v.z, cRZ * v.w);
        v = whh4[(2 * HH + lane) * 8 + k4];
        wa2[2*k4]   = pack2(cA * v.x, cA * v.y);
        wa2[2*k4+1] = pack2(cA * v.z, cA * v.w);
    }

    // Input-gate weights + biases, pre-scaled the same way
    const float wir0 = cRZ * Wih[(0*HH + lane)*DD + 0];
    const float wir1 = cRZ * Wih[(0*HH + lane)*DD + 1];
    const float wir2 = cRZ * Wih[(0*HH + lane)*DD + 2];
    const float wiz0 = cRZ * Wih[(1*HH + lane)*DD + 0];
    const float wiz1 = cRZ * Wih[(1*HH + lane)*DD + 1];
    const float wiz2 = cRZ * Wih[(1*HH + lane)*DD + 2];
    const float wia0 = cA  * Wih[(2*HH + lane)*DD + 0];
    const float wia1 = cA  * Wih[(2*HH + lane)*DD + 1];
    const float wia2 = cA  * Wih[(2*HH + lane)*DD + 2];
    const float br = cRZ * bias[0*HH + lane];
    const float bz = cRZ * bias[1*HH + lane];
    const float ba = cA  * (bias[2*HH + lane] + bias_n[lane]);

    const float4* __restrict__ x4 = reinterpret_cast<const float4*>(inp + (size_t)b * TT * DD);
    float*        __restrict__ op = out + (size_t)b * TT;

    float h = 0.0f;
    int buf = 0;

    // First group of 4 steps (12 floats = 3x float4)
    float4 xa = x4[0], xb = x4[1], xc = x4[2];

    //  pr = -L*(ir + W_r.h)        -> r = 1/(1+2^pr) = sigmoid(ir+hr)
    //  pz = -L*(iz + W_z.h)        -> z likewise
    //  arg= -2L*(ia + ban + r*ha)  -> n = 2/(1+2^arg) - 1 = tanh(...)
    #define GRU_STEP(X0, X1, X2, TIDX)                                          \
    {                                                                           \
        float ir = fmaf(wir2, (X2), fmaf(wir1, (X1), fmaf(wir0, (X0), br)));    \
        float iz = fmaf(wiz2, (X2), fmaf(wiz1, (X1), fmaf(wiz0, (X0), bz)));    \
        float ia = fmaf(wia2, (X2), fmaf(wia1, (X1), fmaf(wia0, (X0), ba)));    \
        hsh[wid][buf][lane] = h;                                                \
        __syncwarp();                                                           \
        const ulonglong2* hb = reinterpret_cast<const ulonglong2*>(hsh[wid][buf]); \
        ull pr = pack2(ir, 0.0f);                                               \
        ull pz = pack2(iz, 0.0f);                                               \
        ull pa = pack2(0.0f, 0.0f);                                             \
        _Pragma("unroll")                                                       \
        for (int q = 0; q < 8; q++) {                                           \
            const ulonglong2 hv = hb[q];  /* (h[4q],h[4q+1]),(h[4q+2],h[4q+3]) */ \
            pr = ffma2(wr2[2*q],   hv.x, pr);                                   \
            pr = ffma2(wr2[2*q+1], hv.y, pr);                                   \
            pz = ffma2(wz2[2*q],   hv.x, pz);                                   \
            pz = ffma2(wz2[2*q+1], hv.y, pz);                                   \
            pa = ffma2(wa2[2*q],   hv.x, pa);                                   \
            pa = ffma2(wa2[2*q+1], hv.y, pa);                                   \
        }                                                                       \
        float rl, rh, zl, zh, al, ah;                                           \
        unpack2(pr, rl, rh);                                                    \
        unpack2(pz, zl, zh);                                                    \
        unpack2(pa, al, ah);                                                    \
        const float r  = rcpf(1.0f + ex2f(rl + rh));                            \
        const float z  = rcpf(1.0f + ex2f(zl + zh));                            \
        const float tn = rcpf(1.0f + ex2f(fmaf(r, al + ah, ia)));               \
        const float n  = fmaf(2.0f, tn, -1.0f);                                 \
        h = fmaf(z, h - n, n);                                                  \
        buf ^= 1;                                                               \
        if (lane == 0) op[TIDX] = h;                                            \
    }

    const int NG = TT / 4;
    for (int g = 0; g < NG; g++) {
        const int gn3 = ((g + 1 < NG) ? (g + 1) : g) * 3;  // next group (clamped)
        const int t0  = g * 4;

        GRU_STEP(xa.x, xa.y, xa.z, t0);
        GRU_STEP(xa.w, xb.x, xb.y, t0 + 1);
        xa = x4[gn3 + 0];                 // reload right after last use of xa
        GRU_STEP(xb.z, xb.w, xc.x, t0 + 2);
        xb = x4[gn3 + 1];
        GRU_STEP(xc.y, xc.z, xc.w, t0 + 3);
        xc = x4[gn3 + 2];
    }
    #undef GRU_STEP
}

extern "C" void kernel_launch(void* const* d_in, const int* in_sizes, int n_in,
                              void* d_out, int out_size) {
    const float* inp    = (const float*)d_in[0];
    const float* wih    = (const float*)d_in[1];
    const float* whh    = (const float*)d_in[2];
    const float* bias   = (const float*)d_in[3];
    const float* bias_n = (const float*)d_in[4];
    float* out = (float*)d_out;

    // 512 CTAs x 128 threads: 4 warps/CTA -> all 4 SMSPs populated
    gru_scan_kernel<<<BB / 4, 128>>>(inp, wih, whh, bias, bias_n, out);
}